// round 1
// baseline (speedup 1.0000x reference)
#include <cuda_runtime.h>

// ---------------- problem constants ----------------
#define N_  100000
#define E_  3200000
#define D_  128
#define G_  64
#define C_  4

// ---------------- static device scratch ----------------
__device__ float g_hsum[N_ * D_];    // h + sum_neighbors
__device__ float g_tmp [N_ * D_];    // after first Linear/BN/ReLU of a conv
__device__ float g_h   [N_ * D_];    // after second Linear/BN/ReLU (layer output)
__device__ int   g_deg [N_];
__device__ int   g_cur [N_];
__device__ int   g_rowptr[N_ + 1];
__device__ int   g_csr [E_];
__device__ float g_pooled[G_ * D_];

// ---------------- CSR build ----------------
__global__ void k_zero() {
    int i = blockIdx.x * blockDim.x + threadIdx.x;
    if (i < N_) { g_deg[i] = 0; g_cur[i] = 0; }
    if (i < G_ * D_) g_pooled[i] = 0.0f;
}

__global__ void k_hist(const int* __restrict__ ei) {
    int e = blockIdx.x * blockDim.x + threadIdx.x;
    if (e < E_) atomicAdd(&g_deg[ei[E_ + e]], 1);   // dst = ei[1][e]
}

// single-block exclusive scan of g_deg -> g_rowptr (N=100000, 98 chunks of 1024)
__global__ void k_scan() {
    __shared__ int s[1024];
    int tid = threadIdx.x;
    int carry = 0;
    for (int base = 0; base < N_; base += 1024) {
        int i = base + tid;
        int v = (i < N_) ? g_deg[i] : 0;
        s[tid] = v;
        __syncthreads();
        #pragma unroll
        for (int off = 1; off < 1024; off <<= 1) {
            int t = 0;
            if (tid >= off) t = s[tid - off];
            __syncthreads();
            s[tid] += t;
            __syncthreads();
        }
        if (i < N_) g_rowptr[i] = carry + s[tid] - v;  // exclusive
        carry += s[1023];
        __syncthreads();
    }
    if (tid == 0) g_rowptr[N_] = carry;
}

__global__ void k_scatter(const int* __restrict__ ei) {
    int e = blockIdx.x * blockDim.x + threadIdx.x;
    if (e < E_) {
        int d   = ei[E_ + e];
        int pos = g_rowptr[d] + atomicAdd(&g_cur[d], 1);
        g_csr[pos] = ei[e];                            // src = ei[0][e]
    }
}

// ---------------- SpMM: hsum = h + sum_{j->i} h_j (warp per node) ----------------
__global__ void k_spmm(const float* __restrict__ h) {
    int node = (blockIdx.x * blockDim.x + threadIdx.x) >> 5;
    if (node >= N_) return;
    int lane = threadIdx.x & 31;
    const float4* h4 = (const float4*)h;
    float4 acc = h4[node * 32 + lane];                 // self term (eps = 0)
    int beg = g_rowptr[node], end = g_rowptr[node + 1];
    for (int e = beg; e < end; e += 32) {
        int cnt = end - e; if (cnt > 32) cnt = 32;
        int idx = 0;
        if (lane < cnt) idx = g_csr[e + lane];
        for (int j = 0; j < cnt; j++) {
            int nbr = __shfl_sync(0xffffffffu, idx, j);
            float4 v = h4[nbr * 32 + lane];
            acc.x += v.x; acc.y += v.y; acc.z += v.z; acc.w += v.w;
        }
    }
    *(float4*)&g_hsum[node * D_ + lane * 4] = acc;
}

// ---------------- fused GEMM + BN(eval) + ReLU ----------------
// Out[r][c] = relu( (A[r,:] @ W[:,c] + bias[c] - mean[c]) * gamma[c]/sqrt(var[c]+eps) + beta[c] )
// BM=128, BN=128 (=D), BK=16, 256 threads, 8x8 per thread.
__global__ void __launch_bounds__(256) k_gemm(
    const float* __restrict__ A, const float* __restrict__ W,
    const float* __restrict__ bias, const float* __restrict__ gamma,
    const float* __restrict__ beta, const float* __restrict__ mean,
    const float* __restrict__ var, float* __restrict__ Out, int M)
{
    __shared__ float As[16][128];   // As[k][m]  (transposed on store)
    __shared__ float Bs[16][128];   // Bs[k][n]
    __shared__ float s_scale[128], s_shift[128];

    int tid = threadIdx.x;
    if (tid < 128) {
        float sc = gamma[tid] * rsqrtf(var[tid] + 1e-5f);
        s_scale[tid] = sc;
        s_shift[tid] = (bias[tid] - mean[tid]) * sc + beta[tid];
    }
    int row0 = blockIdx.x * 128;
    int tx = tid & 15, ty = tid >> 4;

    float acc[8][8];
    #pragma unroll
    for (int m = 0; m < 8; m++)
        #pragma unroll
        for (int n = 0; n < 8; n++) acc[m][n] = 0.0f;

    for (int k0 = 0; k0 < 128; k0 += 16) {
        // A tile: 128x16, float4 loads, store transposed
        #pragma unroll
        for (int t = 0; t < 2; t++) {
            int i4 = tid + t * 256;
            int r = i4 >> 2, c4 = i4 & 3;
            float4 v = make_float4(0.f, 0.f, 0.f, 0.f);
            int gr = row0 + r;
            if (gr < M) v = *(const float4*)&A[gr * 128 + k0 + c4 * 4];
            As[c4 * 4 + 0][r] = v.x;
            As[c4 * 4 + 1][r] = v.y;
            As[c4 * 4 + 2][r] = v.z;
            As[c4 * 4 + 3][r] = v.w;
        }
        // B tile: 16x128
        #pragma unroll
        for (int t = 0; t < 2; t++) {
            int i4 = tid + t * 256;
            int r = i4 >> 5, c4 = i4 & 31;
            *(float4*)&Bs[r][c4 * 4] = *(const float4*)&W[(k0 + r) * 128 + c4 * 4];
        }
        __syncthreads();

        #pragma unroll
        for (int kk = 0; kk < 16; kk++) {
            float4 a0 = *(const float4*)&As[kk][ty * 8];
            float4 a1 = *(const float4*)&As[kk][ty * 8 + 4];
            float4 b0 = *(const float4*)&Bs[kk][tx * 8];
            float4 b1 = *(const float4*)&Bs[kk][tx * 8 + 4];
            float a[8] = {a0.x, a0.y, a0.z, a0.w, a1.x, a1.y, a1.z, a1.w};
            float b[8] = {b0.x, b0.y, b0.z, b0.w, b1.x, b1.y, b1.z, b1.w};
            #pragma unroll
            for (int m = 0; m < 8; m++)
                #pragma unroll
                for (int n = 0; n < 8; n++)
                    acc[m][n] += a[m] * b[n];
        }
        __syncthreads();
    }

    // epilogue: BN(eval) + ReLU
    #pragma unroll
    for (int m = 0; m < 8; m++) {
        int gr = row0 + ty * 8 + m;
        if (gr >= M) break;
        #pragma unroll
        for (int n = 0; n < 8; n += 4) {
            int c = tx * 8 + n;
            float4 o;
            o.x = fmaxf(acc[m][n + 0] * s_scale[c + 0] + s_shift[c + 0], 0.0f);
            o.y = fmaxf(acc[m][n + 1] * s_scale[c + 1] + s_shift[c + 1], 0.0f);
            o.z = fmaxf(acc[m][n + 2] * s_scale[c + 2] + s_shift[c + 2], 0.0f);
            o.w = fmaxf(acc[m][n + 3] * s_scale[c + 3] + s_shift[c + 3], 0.0f);
            *(float4*)&Out[gr * 128 + c] = o;
        }
    }
}

// ---------------- segment_max pool (h >= 0 after ReLU => float-bits atomicMax valid) ----------------
__global__ void k_pool(const int* __restrict__ batch) {
    int t  = threadIdx.x;                 // 0..127, one feature dim
    int n0 = blockIdx.x * 128;
    int n1 = n0 + 128; if (n1 > N_) n1 = N_;
    int curg = batch[n0];
    float m = 0.0f;
    for (int n = n0; n < n1; n++) {
        int g = batch[n];
        if (g != curg) {
            atomicMax((unsigned int*)&g_pooled[curg * D_ + t], __float_as_uint(m));
            m = 0.0f; curg = g;
        }
        m = fmaxf(m, g_h[n * D_ + t]);
    }
    atomicMax((unsigned int*)&g_pooled[curg * D_ + t], __float_as_uint(m));
}

// ---------------- classifier head + log_softmax ----------------
__global__ void k_head(const float* __restrict__ lw, const float* __restrict__ lb,
                       float* __restrict__ out) {
    int g = threadIdx.x;
    if (g >= G_) return;
    float lg[4] = {lb[0], lb[1], lb[2], lb[3]};
    for (int d = 0; d < D_; d++) {
        float p = g_pooled[g * D_ + d];
        #pragma unroll
        for (int c = 0; c < C_; c++) lg[c] += p * lw[d * C_ + c];
    }
    float mx = fmaxf(fmaxf(lg[0], lg[1]), fmaxf(lg[2], lg[3]));
    float s = 0.0f;
    #pragma unroll
    for (int c = 0; c < C_; c++) s += expf(lg[c] - mx);
    float ls = logf(s) + mx;
    #pragma unroll
    for (int c = 0; c < C_; c++) out[g * C_ + c] = lg[c] - ls;
}

// ---------------- host launcher ----------------
extern "C" void kernel_launch(void* const* d_in, const int* in_sizes, int n_in,
                              void* d_out, int out_size) {
    const float* x      = (const float*)d_in[0];
    const int*   ei     = (const int*)  d_in[1];
    const int*   batch  = (const int*)  d_in[2];
    const float* Ws     = (const float*)d_in[3];
    const float* bs     = (const float*)d_in[4];
    const float* gammas = (const float*)d_in[5];
    const float* betas  = (const float*)d_in[6];
    const float* means  = (const float*)d_in[7];
    const float* vars   = (const float*)d_in[8];
    const float* lw     = (const float*)d_in[9];
    const float* lb     = (const float*)d_in[10];
    float* out = (float*)d_out;

    float *hsum, *tmp, *h;
    cudaGetSymbolAddress((void**)&hsum, g_hsum);
    cudaGetSymbolAddress((void**)&tmp,  g_tmp);
    cudaGetSymbolAddress((void**)&h,    g_h);

    const int ZB = ((N_ > G_ * D_ ? N_ : G_ * D_) + 255) / 256;
    const int EB = (E_ + 255) / 256;
    const int SB = (N_ * 32 + 255) / 256;
    const int MB = (N_ + 127) / 128;

    // CSR build (per launch; replayed identically by the graph)
    k_zero<<<ZB, 256>>>();
    k_hist<<<EB, 256>>>(ei);
    k_scan<<<1, 1024>>>();
    k_scatter<<<EB, 256>>>(ei);

    // 3 GIN convs
    for (int l = 0; l < 3; l++) {
        const float* hin = (l == 0) ? x : h;
        k_spmm<<<SB, 256>>>(hin);
        int i0 = l * 2 + 0, i1 = l * 2 + 1;
        k_gemm<<<MB, 256>>>(hsum, Ws + i0 * 128 * 128,
                            bs + i0 * 128, gammas + i0 * 128, betas + i0 * 128,
                            means + i0 * 128, vars + i0 * 128, tmp, N_);
        k_gemm<<<MB, 256>>>(tmp, Ws + i1 * 128 * 128,
                            bs + i1 * 128, gammas + i1 * 128, betas + i1 * 128,
                            means + i1 * 128, vars + i1 * 128, h, N_);
    }

    // pool + head
    k_pool<<<MB, 128>>>(batch);
    k_head<<<1, 64>>>(lw, lb, out);
}

// round 2
// speedup vs baseline: 1.2864x; 1.2864x over previous
#include <cuda_runtime.h>
#include <cuda_bf16.h>

// ---------------- problem constants ----------------
#define N_  100000
#define E_  3200000
#define D_  128
#define G_  64
#define C_  4

// ---------------- static device scratch ----------------
__device__ float g_hsum[N_ * D_];
__device__ float g_tmp [N_ * D_];
__device__ float g_h   [N_ * D_];
__device__ int   g_deg [N_];
__device__ int   g_cur [N_];
__device__ int   g_rowptr[N_ + 1];
__device__ int   g_csr [E_];
__device__ float g_pooled[G_ * D_];
// per-layer transposed bf16 weight splits: Wt[n][k]
__device__ __nv_bfloat16 g_wh[6 * D_ * D_];
__device__ __nv_bfloat16 g_wl[6 * D_ * D_];

// ---------------- CSR build ----------------
__global__ void k_zero() {
    int i = blockIdx.x * blockDim.x + threadIdx.x;
    if (i < N_) { g_deg[i] = 0; g_cur[i] = 0; }
    if (i < G_ * D_) g_pooled[i] = 0.0f;
}

__global__ void k_hist(const int* __restrict__ ei) {
    int e = blockIdx.x * blockDim.x + threadIdx.x;
    if (e < E_) atomicAdd(&g_deg[ei[E_ + e]], 1);   // dst
}

__global__ void k_scan() {
    __shared__ int s[1024];
    int tid = threadIdx.x;
    int carry = 0;
    for (int base = 0; base < N_; base += 1024) {
        int i = base + tid;
        int v = (i < N_) ? g_deg[i] : 0;
        s[tid] = v;
        __syncthreads();
        #pragma unroll
        for (int off = 1; off < 1024; off <<= 1) {
            int t = 0;
            if (tid >= off) t = s[tid - off];
            __syncthreads();
            s[tid] += t;
            __syncthreads();
        }
        if (i < N_) g_rowptr[i] = carry + s[tid] - v;
        carry += s[1023];
        __syncthreads();
    }
    if (tid == 0) g_rowptr[N_] = carry;
}

__global__ void k_scatter(const int* __restrict__ ei) {
    int e = blockIdx.x * blockDim.x + threadIdx.x;
    if (e < E_) {
        int d   = ei[E_ + e];
        int pos = g_rowptr[d] + atomicAdd(&g_cur[d], 1);
        g_csr[pos] = ei[e];
    }
}

// ---------------- SpMM: hsum = h + sum_{j->i} h_j ----------------
__global__ void k_spmm(const float* __restrict__ h) {
    int node = (blockIdx.x * blockDim.x + threadIdx.x) >> 5;
    if (node >= N_) return;
    int lane = threadIdx.x & 31;
    const float4* h4 = (const float4*)h;
    float4 acc = h4[node * 32 + lane];
    int beg = g_rowptr[node], end = g_rowptr[node + 1];
    for (int e = beg; e < end; e += 32) {
        int cnt = end - e; if (cnt > 32) cnt = 32;
        int idx = 0;
        if (lane < cnt) idx = g_csr[e + lane];
        for (int j = 0; j < cnt; j++) {
            int nbr = __shfl_sync(0xffffffffu, idx, j);
            float4 v = h4[nbr * 32 + lane];
            acc.x += v.x; acc.y += v.y; acc.z += v.z; acc.w += v.w;
        }
    }
    *(float4*)&g_hsum[node * D_ + lane * 4] = acc;
}

// ---------------- weight split/transpose: Wt_hi/Wt_lo[n][k] ----------------
__global__ void k_wsplit(const float* __restrict__ Ws) {
    int l = blockIdx.x;                       // layer-linear index 0..5
    const float* W = Ws + l * D_ * D_;
    __nv_bfloat16* wh = g_wh + l * D_ * D_;
    __nv_bfloat16* wl = g_wl + l * D_ * D_;
    for (int i = threadIdx.x; i < D_ * D_; i += blockDim.x) {
        int k = i >> 7, n = i & 127;
        float w = W[i];
        __nv_bfloat16 hi = __float2bfloat16(w);
        float r = w - __bfloat162float(hi);
        wh[n * D_ + k] = hi;
        wl[n * D_ + k] = __float2bfloat16(r);
    }
}

// ---------------- tensor-core GEMM + BN(eval) + ReLU ----------------
// Out[r][c] = relu((A@W)[r][c] * scale[c] + shift[c]) via bf16 hi/lo split.
// BM=128, BN=128(=D), full K=128 in chunks of 32. 256 threads, 8 warps (2x4).
#define WT_STRIDE 136   // halves, padded (272B rows -> conflict-free B frags)
#define AS_STRIDE 40    // halves, padded (80B rows  -> conflict-free A frags)
#define SM_WH   0
#define SM_WL   (D_ * WT_STRIDE)
#define SM_AH   (2 * D_ * WT_STRIDE)
#define SM_AL   (2 * D_ * WT_STRIDE + D_ * AS_STRIDE)
#define SM_HALVES (2 * D_ * WT_STRIDE + 2 * D_ * AS_STRIDE)
#define SM_BYTES  (SM_HALVES * 2 + 2 * D_ * 4)

__device__ __forceinline__ void mma16816(float* d, const unsigned* a,
                                         unsigned b0, unsigned b1) {
    asm volatile(
        "mma.sync.aligned.m16n8k16.row.col.f32.bf16.bf16.f32 "
        "{%0,%1,%2,%3},{%4,%5,%6,%7},{%8,%9},{%0,%1,%2,%3};\n"
        : "+f"(d[0]), "+f"(d[1]), "+f"(d[2]), "+f"(d[3])
        : "r"(a[0]), "r"(a[1]), "r"(a[2]), "r"(a[3]), "r"(b0), "r"(b1));
}

__global__ void __launch_bounds__(256) k_gemm_t(
    const float* __restrict__ A,
    const __nv_bfloat16* __restrict__ wtg_hi,
    const __nv_bfloat16* __restrict__ wtg_lo,
    const float* __restrict__ bias, const float* __restrict__ gamma,
    const float* __restrict__ beta, const float* __restrict__ mean,
    const float* __restrict__ var, float* __restrict__ Out, int M)
{
    extern __shared__ __nv_bfloat16 sm[];
    __nv_bfloat16* Wh = sm + SM_WH;
    __nv_bfloat16* Wl = sm + SM_WL;
    __nv_bfloat16* Ah = sm + SM_AH;
    __nv_bfloat16* Al = sm + SM_AL;
    float* s_scale = (float*)(sm + SM_HALVES);
    float* s_shift = s_scale + D_;

    const int tid  = threadIdx.x;
    const int lane = tid & 31;
    const int wid  = tid >> 5;
    const int warpRow = (wid >> 2) * 64;   // 2 warp-rows
    const int warpCol = (wid & 3) * 32;    // 4 warp-cols
    const int row0 = blockIdx.x * 128;

    // stage W (bf16, repad 128 -> 136 halves per row)
    {
        const uint4* sh = (const uint4*)wtg_hi;
        const uint4* sl = (const uint4*)wtg_lo;
        for (int i = tid; i < 2048; i += 256) {       // 2048 x 16B = 32KB each
            int n = i >> 4, q = i & 15;
            *(uint4*)(Wh + n * WT_STRIDE + q * 8) = sh[i];
            *(uint4*)(Wl + n * WT_STRIDE + q * 8) = sl[i];
        }
    }
    if (tid < 128) {
        float sc = gamma[tid] * rsqrtf(var[tid] + 1e-5f);
        s_scale[tid] = sc;
        s_shift[tid] = (bias[tid] - mean[tid]) * sc + beta[tid];
    }

    float acc[4][4][4];
    #pragma unroll
    for (int m = 0; m < 4; m++)
        #pragma unroll
        for (int n = 0; n < 4; n++)
            #pragma unroll
            for (int i = 0; i < 4; i++) acc[m][n][i] = 0.0f;

    for (int kc = 0; kc < 128; kc += 32) {
        __syncthreads();
        // stage A chunk 128x32 fp32 -> hi/lo bf16
        #pragma unroll
        for (int t = 0; t < 4; t++) {
            int p = tid + t * 256;         // 1024 float4s
            int r = p >> 3, q = p & 7;
            int k = q * 4;
            float4 v = make_float4(0.f, 0.f, 0.f, 0.f);
            int gr = row0 + r;
            if (gr < M) v = *(const float4*)&A[gr * 128 + kc + k];
            float f[4] = {v.x, v.y, v.z, v.w};
            __nv_bfloat162 h2[2], l2[2];
            #pragma unroll
            for (int j = 0; j < 2; j++) {
                __nv_bfloat16 h0 = __float2bfloat16(f[j * 2]);
                __nv_bfloat16 h1 = __float2bfloat16(f[j * 2 + 1]);
                float r0 = f[j * 2]     - __bfloat162float(h0);
                float r1 = f[j * 2 + 1] - __bfloat162float(h1);
                h2[j] = __nv_bfloat162(h0, h1);
                l2[j] = __nv_bfloat162(__float2bfloat16(r0), __float2bfloat16(r1));
            }
            *(__nv_bfloat162*)(Ah + r * AS_STRIDE + k)     = h2[0];
            *(__nv_bfloat162*)(Ah + r * AS_STRIDE + k + 2) = h2[1];
            *(__nv_bfloat162*)(Al + r * AS_STRIDE + k)     = l2[0];
            *(__nv_bfloat162*)(Al + r * AS_STRIDE + k + 2) = l2[1];
        }
        __syncthreads();

        #pragma unroll
        for (int kk = 0; kk < 32; kk += 16) {
            unsigned ah[4][4], al[4][4];
            #pragma unroll
            for (int mt = 0; mt < 4; mt++) {
                int r = warpRow + mt * 16 + (lane >> 2);
                int ko = kk + (lane & 3) * 2;
                ah[mt][0] = *(unsigned*)(Ah + r * AS_STRIDE + ko);
                ah[mt][1] = *(unsigned*)(Ah + (r + 8) * AS_STRIDE + ko);
                ah[mt][2] = *(unsigned*)(Ah + r * AS_STRIDE + ko + 8);
                ah[mt][3] = *(unsigned*)(Ah + (r + 8) * AS_STRIDE + ko + 8);
                al[mt][0] = *(unsigned*)(Al + r * AS_STRIDE + ko);
                al[mt][1] = *(unsigned*)(Al + (r + 8) * AS_STRIDE + ko);
                al[mt][2] = *(unsigned*)(Al + r * AS_STRIDE + ko + 8);
                al[mt][3] = *(unsigned*)(Al + (r + 8) * AS_STRIDE + ko + 8);
            }
            #pragma unroll
            for (int nt = 0; nt < 4; nt++) {
                int n = warpCol + nt * 8 + (lane >> 2);
                int ko = kc + kk + (lane & 3) * 2;
                unsigned bh0 = *(unsigned*)(Wh + n * WT_STRIDE + ko);
                unsigned bh1 = *(unsigned*)(Wh + n * WT_STRIDE + ko + 8);
                unsigned bl0 = *(unsigned*)(Wl + n * WT_STRIDE + ko);
                unsigned bl1 = *(unsigned*)(Wl + n * WT_STRIDE + ko + 8);
                #pragma unroll
                for (int mt = 0; mt < 4; mt++) {
                    mma16816(acc[mt][nt], ah[mt], bh0, bh1);
                    mma16816(acc[mt][nt], al[mt], bh0, bh1);
                    mma16816(acc[mt][nt], ah[mt], bl0, bl1);
                }
            }
        }
    }

    // epilogue: BN(eval) + ReLU
    #pragma unroll
    for (int mt = 0; mt < 4; mt++) {
        #pragma unroll
        for (int half = 0; half < 2; half++) {
            int gr = row0 + warpRow + mt * 16 + (lane >> 2) + half * 8;
            if (gr >= M) continue;
            #pragma unroll
            for (int nt = 0; nt < 4; nt++) {
                int c = warpCol + nt * 8 + (lane & 3) * 2;
                float v0 = acc[mt][nt][half * 2 + 0];
                float v1 = acc[mt][nt][half * 2 + 1];
                float2 o;
                o.x = fmaxf(v0 * s_scale[c]     + s_shift[c],     0.0f);
                o.y = fmaxf(v1 * s_scale[c + 1] + s_shift[c + 1], 0.0f);
                *(float2*)&Out[gr * 128 + c] = o;
            }
        }
    }
}

// ---------------- segment_max pool ----------------
__global__ void k_pool(const int* __restrict__ batch) {
    int t  = threadIdx.x;
    int n0 = blockIdx.x * 128;
    int n1 = n0 + 128; if (n1 > N_) n1 = N_;
    int curg = batch[n0];
    float m = 0.0f;
    for (int n = n0; n < n1; n++) {
        int g = batch[n];
        if (g != curg) {
            atomicMax((unsigned int*)&g_pooled[curg * D_ + t], __float_as_uint(m));
            m = 0.0f; curg = g;
        }
        m = fmaxf(m, g_h[n * D_ + t]);
    }
    atomicMax((unsigned int*)&g_pooled[curg * D_ + t], __float_as_uint(m));
}

// ---------------- classifier head + log_softmax ----------------
__global__ void k_head(const float* __restrict__ lw, const float* __restrict__ lb,
                       float* __restrict__ out) {
    int g = threadIdx.x;
    if (g >= G_) return;
    float lg[4] = {lb[0], lb[1], lb[2], lb[3]};
    for (int d = 0; d < D_; d++) {
        float p = g_pooled[g * D_ + d];
        #pragma unroll
        for (int c = 0; c < C_; c++) lg[c] += p * lw[d * C_ + c];
    }
    float mx = fmaxf(fmaxf(lg[0], lg[1]), fmaxf(lg[2], lg[3]));
    float s = 0.0f;
    #pragma unroll
    for (int c = 0; c < C_; c++) s += expf(lg[c] - mx);
    float ls = logf(s) + mx;
    #pragma unroll
    for (int c = 0; c < C_; c++) out[g * C_ + c] = lg[c] - ls;
}

// ---------------- host launcher ----------------
extern "C" void kernel_launch(void* const* d_in, const int* in_sizes, int n_in,
                              void* d_out, int out_size) {
    const float* x      = (const float*)d_in[0];
    const int*   ei     = (const int*)  d_in[1];
    const int*   batch  = (const int*)  d_in[2];
    const float* Ws     = (const float*)d_in[3];
    const float* bs     = (const float*)d_in[4];
    const float* gammas = (const float*)d_in[5];
    const float* betas  = (const float*)d_in[6];
    const float* means  = (const float*)d_in[7];
    const float* vars   = (const float*)d_in[8];
    const float* lw     = (const float*)d_in[9];
    const float* lb     = (const float*)d_in[10];
    float* out = (float*)d_out;

    float *hsum, *tmp, *h;
    __nv_bfloat16 *wh, *wl;
    cudaGetSymbolAddress((void**)&hsum, g_hsum);
    cudaGetSymbolAddress((void**)&tmp,  g_tmp);
    cudaGetSymbolAddress((void**)&h,    g_h);
    cudaGetSymbolAddress((void**)&wh,   g_wh);
    cudaGetSymbolAddress((void**)&wl,   g_wl);

    static bool attr_done = false;
    if (!attr_done) {
        cudaFuncSetAttribute(k_gemm_t, cudaFuncAttributeMaxDynamicSharedMemorySize,
                             SM_BYTES);
        attr_done = true;
    }

    const int ZB = ((N_ > G_ * D_ ? N_ : G_ * D_) + 255) / 256;
    const int EB = (E_ + 255) / 256;
    const int SB = (N_ * 32 + 255) / 256;
    const int MB = (N_ + 127) / 128;

    // CSR build + weight split (independent)
    k_zero<<<ZB, 256>>>();
    k_wsplit<<<6, 256>>>(Ws);
    k_hist<<<EB, 256>>>(ei);
    k_scan<<<1, 1024>>>();
    k_scatter<<<EB, 256>>>(ei);

    // 3 GIN convs
    for (int l = 0; l < 3; l++) {
        const float* hin = (l == 0) ? x : h;
        k_spmm<<<SB, 256>>>(hin);
        int i0 = l * 2 + 0, i1 = l * 2 + 1;
        k_gemm_t<<<MB, 256, SM_BYTES>>>(hsum, wh + i0 * D_ * D_, wl + i0 * D_ * D_,
                            bs + i0 * 128, gammas + i0 * 128, betas + i0 * 128,
                            means + i0 * 128, vars + i0 * 128, tmp, N_);
        k_gemm_t<<<MB, 256, SM_BYTES>>>(tmp, wh + i1 * D_ * D_, wl + i1 * D_ * D_,
                            bs + i1 * 128, gammas + i1 * 128, betas + i1 * 128,
                            means + i1 * 128, vars + i1 * 128, h, N_);
    }

    // pool + head
    k_pool<<<MB, 128>>>(batch);
    k_head<<<1, 64>>>(lw, lb, out);
}

// round 3
// speedup vs baseline: 1.4916x; 1.1595x over previous
#include <cuda_runtime.h>
#include <cuda_bf16.h>

// ---------------- problem constants ----------------
#define N_  100000
#define E_  3200000
#define D_  128
#define G_  64
#define C_  4
#define SCAN_CHUNK 1024
#define SCAN_BLOCKS ((N_ + SCAN_CHUNK - 1) / SCAN_CHUNK)   // 98

// ---------------- static device scratch ----------------
__device__ float g_hsum[N_ * D_];
__device__ float g_tmp [N_ * D_];
__device__ float g_h   [N_ * D_];
__device__ int   g_deg [N_];
__device__ int   g_cur [N_];
__device__ int   g_rowptr[N_ + 1];
__device__ int   g_bsum[SCAN_BLOCKS];
__device__ int   g_csr [E_];
__device__ float g_pooled[G_ * D_];
__device__ __nv_bfloat16 g_wh[6 * D_ * D_];
__device__ __nv_bfloat16 g_wl[6 * D_ * D_];

// ---------------- CSR build ----------------
__global__ void k_zero() {
    int i = blockIdx.x * blockDim.x + threadIdx.x;
    if (i < N_) { g_deg[i] = 0; g_cur[i] = 0; }
    if (i < G_ * D_) g_pooled[i] = 0.0f;
}

__global__ void k_hist(const int* __restrict__ ei) {
    int e = blockIdx.x * blockDim.x + threadIdx.x;
    if (e < E_) atomicAdd(&g_deg[ei[E_ + e]], 1);   // dst
}

// ---- device-wide exclusive scan of g_deg -> g_rowptr, 3 phases ----
__global__ void k_scan1() {
    __shared__ int s[SCAN_CHUNK];
    int tid = threadIdx.x;
    int i = blockIdx.x * SCAN_CHUNK + tid;
    int v = (i < N_) ? g_deg[i] : 0;
    s[tid] = v;
    __syncthreads();
    #pragma unroll
    for (int off = 1; off < SCAN_CHUNK; off <<= 1) {
        int t = 0;
        if (tid >= off) t = s[tid - off];
        __syncthreads();
        s[tid] += t;
        __syncthreads();
    }
    if (i < N_) g_rowptr[i] = s[tid] - v;            // block-local exclusive
    if (tid == SCAN_CHUNK - 1) g_bsum[blockIdx.x] = s[tid];
}

__global__ void k_scan2() {                           // 1 block, 128 threads
    __shared__ int s[128];
    int tid = threadIdx.x;
    int v = (tid < SCAN_BLOCKS) ? g_bsum[tid] : 0;
    s[tid] = v;
    __syncthreads();
    #pragma unroll
    for (int off = 1; off < 128; off <<= 1) {
        int t = 0;
        if (tid >= off) t = s[tid - off];
        __syncthreads();
        s[tid] += t;
        __syncthreads();
    }
    if (tid < SCAN_BLOCKS) g_bsum[tid] = s[tid] - v; // exclusive
    if (tid == 0) g_rowptr[N_] = E_;                 // degree sum is always E
}

__global__ void k_scan3() {
    int i = blockIdx.x * SCAN_CHUNK + threadIdx.x;
    if (i < N_ && blockIdx.x > 0) g_rowptr[i] += g_bsum[blockIdx.x];
}

__global__ void k_scatter(const int* __restrict__ ei) {
    int e = blockIdx.x * blockDim.x + threadIdx.x;
    if (e < E_) {
        int d   = ei[E_ + e];
        int pos = g_rowptr[d] + atomicAdd(&g_cur[d], 1);
        g_csr[pos] = ei[e];
    }
}

// ---------------- SpMM: hsum = h + sum_{j->i} h_j ----------------
__global__ void k_spmm(const float* __restrict__ h) {
    int node = (blockIdx.x * blockDim.x + threadIdx.x) >> 5;
    if (node >= N_) return;
    int lane = threadIdx.x & 31;
    const float4* h4 = (const float4*)h;
    float4 acc = h4[node * 32 + lane];
    int beg = g_rowptr[node], end = g_rowptr[node + 1];
    for (int e = beg; e < end; e += 32) {
        int cnt = end - e; if (cnt > 32) cnt = 32;
        int idx = 0;
        if (lane < cnt) idx = g_csr[e + lane];
        for (int j = 0; j < cnt; j++) {
            int nbr = __shfl_sync(0xffffffffu, idx, j);
            float4 v = h4[nbr * 32 + lane];
            acc.x += v.x; acc.y += v.y; acc.z += v.z; acc.w += v.w;
        }
    }
    *(float4*)&g_hsum[node * D_ + lane * 4] = acc;
}

// ---------------- weight split/transpose: Wt_hi/Wt_lo[n][k] ----------------
__global__ void k_wsplit(const float* __restrict__ Ws) {
    int l = blockIdx.x;
    const float* W = Ws + l * D_ * D_;
    __nv_bfloat16* wh = g_wh + l * D_ * D_;
    __nv_bfloat16* wl = g_wl + l * D_ * D_;
    for (int i = threadIdx.x; i < D_ * D_; i += blockDim.x) {
        int k = i >> 7, n = i & 127;
        float w = W[i];
        __nv_bfloat16 hi = __float2bfloat16(w);
        float r = w - __bfloat162float(hi);
        wh[n * D_ + k] = hi;
        wl[n * D_ + k] = __float2bfloat16(r);
    }
}

// ---------------- tensor-core GEMM + BN(eval) + ReLU ----------------
#define WT_STRIDE 136
#define AS_STRIDE 40
#define SM_WH   0
#define SM_WL   (D_ * WT_STRIDE)
#define SM_AH   (2 * D_ * WT_STRIDE)
#define SM_AL   (2 * D_ * WT_STRIDE + D_ * AS_STRIDE)
#define SM_HALVES (2 * D_ * WT_STRIDE + 2 * D_ * AS_STRIDE)
#define SM_BYTES  (SM_HALVES * 2 + 2 * D_ * 4)

__device__ __forceinline__ void mma16816(float* d, const unsigned* a,
                                         unsigned b0, unsigned b1) {
    asm volatile(
        "mma.sync.aligned.m16n8k16.row.col.f32.bf16.bf16.f32 "
        "{%0,%1,%2,%3},{%4,%5,%6,%7},{%8,%9},{%0,%1,%2,%3};\n"
        : "+f"(d[0]), "+f"(d[1]), "+f"(d[2]), "+f"(d[3])
        : "r"(a[0]), "r"(a[1]), "r"(a[2]), "r"(a[3]), "r"(b0), "r"(b1));
}

__global__ void __launch_bounds__(256) k_gemm_t(
    const float* __restrict__ A,
    const __nv_bfloat16* __restrict__ wtg_hi,
    const __nv_bfloat16* __restrict__ wtg_lo,
    const float* __restrict__ bias, const float* __restrict__ gamma,
    const float* __restrict__ beta, const float* __restrict__ mean,
    const float* __restrict__ var, float* __restrict__ Out, int M)
{
    extern __shared__ __nv_bfloat16 sm[];
    __nv_bfloat16* Wh = sm + SM_WH;
    __nv_bfloat16* Wl = sm + SM_WL;
    __nv_bfloat16* Ah = sm + SM_AH;
    __nv_bfloat16* Al = sm + SM_AL;
    float* s_scale = (float*)(sm + SM_HALVES);
    float* s_shift = s_scale + D_;

    const int tid  = threadIdx.x;
    const int lane = tid & 31;
    const int wid  = tid >> 5;
    const int warpRow = (wid >> 2) * 64;
    const int warpCol = (wid & 3) * 32;
    const int row0 = blockIdx.x * 128;

    {
        const uint4* sh = (const uint4*)wtg_hi;
        const uint4* sl = (const uint4*)wtg_lo;
        for (int i = tid; i < 2048; i += 256) {
            int n = i >> 4, q = i & 15;
            *(uint4*)(Wh + n * WT_STRIDE + q * 8) = sh[i];
            *(uint4*)(Wl + n * WT_STRIDE + q * 8) = sl[i];
        }
    }
    if (tid < 128) {
        float sc = gamma[tid] * rsqrtf(var[tid] + 1e-5f);
        s_scale[tid] = sc;
        s_shift[tid] = (bias[tid] - mean[tid]) * sc + beta[tid];
    }

    float acc[4][4][4];
    #pragma unroll
    for (int m = 0; m < 4; m++)
        #pragma unroll
        for (int n = 0; n < 4; n++)
            #pragma unroll
            for (int i = 0; i < 4; i++) acc[m][n][i] = 0.0f;

    for (int kc = 0; kc < 128; kc += 32) {
        __syncthreads();
        #pragma unroll
        for (int t = 0; t < 4; t++) {
            int p = tid + t * 256;
            int r = p >> 3, q = p & 7;
            int k = q * 4;
            float4 v = make_float4(0.f, 0.f, 0.f, 0.f);
            int gr = row0 + r;
            if (gr < M) v = *(const float4*)&A[gr * 128 + kc + k];
            float f[4] = {v.x, v.y, v.z, v.w};
            __nv_bfloat162 h2[2], l2[2];
            #pragma unroll
            for (int j = 0; j < 2; j++) {
                __nv_bfloat16 h0 = __float2bfloat16(f[j * 2]);
                __nv_bfloat16 h1 = __float2bfloat16(f[j * 2 + 1]);
                float r0 = f[j * 2]     - __bfloat162float(h0);
                float r1 = f[j * 2 + 1] - __bfloat162float(h1);
                h2[j] = __nv_bfloat162(h0, h1);
                l2[j] = __nv_bfloat162(__float2bfloat16(r0), __float2bfloat16(r1));
            }
            *(__nv_bfloat162*)(Ah + r * AS_STRIDE + k)     = h2[0];
            *(__nv_bfloat162*)(Ah + r * AS_STRIDE + k + 2) = h2[1];
            *(__nv_bfloat162*)(Al + r * AS_STRIDE + k)     = l2[0];
            *(__nv_bfloat162*)(Al + r * AS_STRIDE + k + 2) = l2[1];
        }
        __syncthreads();

        #pragma unroll
        for (int kk = 0; kk < 32; kk += 16) {
            unsigned ah[4][4], al[4][4];
            #pragma unroll
            for (int mt = 0; mt < 4; mt++) {
                int r = warpRow + mt * 16 + (lane >> 2);
                int ko = kk + (lane & 3) * 2;
                ah[mt][0] = *(unsigned*)(Ah + r * AS_STRIDE + ko);
                ah[mt][1] = *(unsigned*)(Ah + (r + 8) * AS_STRIDE + ko);
                ah[mt][2] = *(unsigned*)(Ah + r * AS_STRIDE + ko + 8);
                ah[mt][3] = *(unsigned*)(Ah + (r + 8) * AS_STRIDE + ko + 8);
                al[mt][0] = *(unsigned*)(Al + r * AS_STRIDE + ko);
                al[mt][1] = *(unsigned*)(Al + (r + 8) * AS_STRIDE + ko);
                al[mt][2] = *(unsigned*)(Al + r * AS_STRIDE + ko + 8);
                al[mt][3] = *(unsigned*)(Al + (r + 8) * AS_STRIDE + ko + 8);
            }
            #pragma unroll
            for (int nt = 0; nt < 4; nt++) {
                int n = warpCol + nt * 8 + (lane >> 2);
                int ko = kc + kk + (lane & 3) * 2;
                unsigned bh0 = *(unsigned*)(Wh + n * WT_STRIDE + ko);
                unsigned bh1 = *(unsigned*)(Wh + n * WT_STRIDE + ko + 8);
                unsigned bl0 = *(unsigned*)(Wl + n * WT_STRIDE + ko);
                unsigned bl1 = *(unsigned*)(Wl + n * WT_STRIDE + ko + 8);
                #pragma unroll
                for (int mt = 0; mt < 4; mt++) {
                    mma16816(acc[mt][nt], ah[mt], bh0, bh1);
                    mma16816(acc[mt][nt], al[mt], bh0, bh1);
                    mma16816(acc[mt][nt], ah[mt], bl0, bl1);
                }
            }
        }
    }

    #pragma unroll
    for (int mt = 0; mt < 4; mt++) {
        #pragma unroll
        for (int half = 0; half < 2; half++) {
            int gr = row0 + warpRow + mt * 16 + (lane >> 2) + half * 8;
            if (gr >= M) continue;
            #pragma unroll
            for (int nt = 0; nt < 4; nt++) {
                int c = warpCol + nt * 8 + (lane & 3) * 2;
                float v0 = acc[mt][nt][half * 2 + 0];
                float v1 = acc[mt][nt][half * 2 + 1];
                float2 o;
                o.x = fmaxf(v0 * s_scale[c]     + s_shift[c],     0.0f);
                o.y = fmaxf(v1 * s_scale[c + 1] + s_shift[c + 1], 0.0f);
                *(float2*)&Out[gr * 128 + c] = o;
            }
        }
    }
}

// ---------------- segment_max pool ----------------
__global__ void k_pool(const int* __restrict__ batch) {
    int t  = threadIdx.x;
    int n0 = blockIdx.x * 128;
    int n1 = n0 + 128; if (n1 > N_) n1 = N_;
    int curg = batch[n0];
    float m = 0.0f;
    for (int n = n0; n < n1; n++) {
        int g = batch[n];
        if (g != curg) {
            atomicMax((unsigned int*)&g_pooled[curg * D_ + t], __float_as_uint(m));
            m = 0.0f; curg = g;
        }
        m = fmaxf(m, g_h[n * D_ + t]);
    }
    atomicMax((unsigned int*)&g_pooled[curg * D_ + t], __float_as_uint(m));
}

// ---------------- classifier head + log_softmax ----------------
__global__ void k_head(const float* __restrict__ lw, const float* __restrict__ lb,
                       float* __restrict__ out) {
    int g = threadIdx.x;
    if (g >= G_) return;
    float lg[4] = {lb[0], lb[1], lb[2], lb[3]};
    for (int d = 0; d < D_; d++) {
        float p = g_pooled[g * D_ + d];
        #pragma unroll
        for (int c = 0; c < C_; c++) lg[c] += p * lw[d * C_ + c];
    }
    float mx = fmaxf(fmaxf(lg[0], lg[1]), fmaxf(lg[2], lg[3]));
    float s = 0.0f;
    #pragma unroll
    for (int c = 0; c < C_; c++) s += expf(lg[c] - mx);
    float ls = logf(s) + mx;
    #pragma unroll
    for (int c = 0; c < C_; c++) out[g * C_ + c] = lg[c] - ls;
}

// ---------------- host launcher ----------------
extern "C" void kernel_launch(void* const* d_in, const int* in_sizes, int n_in,
                              void* d_out, int out_size) {
    const float* x      = (const float*)d_in[0];
    const int*   ei     = (const int*)  d_in[1];
    const int*   batch  = (const int*)  d_in[2];
    const float* Ws     = (const float*)d_in[3];
    const float* bs     = (const float*)d_in[4];
    const float* gammas = (const float*)d_in[5];
    const float* betas  = (const float*)d_in[6];
    const float* means  = (const float*)d_in[7];
    const float* vars   = (const float*)d_in[8];
    const float* lw     = (const float*)d_in[9];
    const float* lb     = (const float*)d_in[10];
    float* out = (float*)d_out;

    float *hsum, *tmp, *h;
    __nv_bfloat16 *wh, *wl;
    cudaGetSymbolAddress((void**)&hsum, g_hsum);
    cudaGetSymbolAddress((void**)&tmp,  g_tmp);
    cudaGetSymbolAddress((void**)&h,    g_h);
    cudaGetSymbolAddress((void**)&wh,   g_wh);
    cudaGetSymbolAddress((void**)&wl,   g_wl);

    static bool attr_done = false;
    if (!attr_done) {
        cudaFuncSetAttribute(k_gemm_t, cudaFuncAttributeMaxDynamicSharedMemorySize,
                             SM_BYTES);
        attr_done = true;
    }

    const int ZB = ((N_ > G_ * D_ ? N_ : G_ * D_) + 255) / 256;
    const int EB = (E_ + 255) / 256;
    const int SB = (N_ * 32 + 255) / 256;
    const int MB = (N_ + 127) / 128;

    // CSR build + weight split
    k_zero<<<ZB, 256>>>();
    k_wsplit<<<6, 256>>>(Ws);
    k_hist<<<EB, 256>>>(ei);
    k_scan1<<<SCAN_BLOCKS, SCAN_CHUNK>>>();
    k_scan2<<<1, 128>>>();
    k_scan3<<<SCAN_BLOCKS, SCAN_CHUNK>>>();
    k_scatter<<<EB, 256>>>(ei);

    // 3 GIN convs
    for (int l = 0; l < 3; l++) {
        const float* hin = (l == 0) ? x : h;
        k_spmm<<<SB, 256>>>(hin);
        int i0 = l * 2 + 0, i1 = l * 2 + 1;
        k_gemm_t<<<MB, 256, SM_BYTES>>>(hsum, wh + i0 * D_ * D_, wl + i0 * D_ * D_,
                            bs + i0 * 128, gammas + i0 * 128, betas + i0 * 128,
                            means + i0 * 128, vars + i0 * 128, tmp, N_);
        k_gemm_t<<<MB, 256, SM_BYTES>>>(tmp, wh + i1 * D_ * D_, wl + i1 * D_ * D_,
                            bs + i1 * 128, gammas + i1 * 128, betas + i1 * 128,
                            means + i1 * 128, vars + i1 * 128, h, N_);
    }

    // pool + head
    k_pool<<<MB, 128>>>(batch);
    k_head<<<1, 64>>>(lw, lb, out);
}